// round 10
// baseline (speedup 1.0000x reference)
#include <cuda_runtime.h>

// AnalyticalBoundedLineAttractor — analytic piecewise-affine ODE integrator.
//
// Per step: z = Wx + b; m = (z>0); x' = x + p1 + p2 with
//   p1 = DT*(relu(z) - x),  p2 = (m .* (W'p1) - DT*p1)/2,  W' = DT*W.
// K = 2 Taylor terms (measured rel_err 4.6e-4 vs 1e-3 gate).
//
// Base architecture (measured best, rounds 3-9): 2 elements per 128-thread
// CTA, grid=128 (one CTA/SM, 4 warps on 4 SMSPs), dot = 16 LDS.128 +
// 32 fma.rn.f32x2, 4 packed accumulators, 99 stored updates.
//
// Round-10: SPLIT-HALF EXCHANGE. Each element's vector halves are produced
// by different warps (warp h owns rows [32h,32h+32)). Consumer starts on
// its OWN half after a 23-cyc __syncwarp while the CROSS half is handed
// over via named-barrier producer/consumer (bar.arrive by producer half,
// bar.sync by consumer) — the bar wait + cross LDS latency hide under
// own-half LDS+FMA work. W registers are loaded own-half-first so all
// register indices stay static. The step-end x exchange is folded into
// the next iteration's first exchange-dot (no loop-end barrier at all).
//
// Safety: every buffer overwrite is ordered after the other warp's last
// read of that buffer through the arrive/sync chain (warp reaches its
// next STS only after bar.sync on the other's arrive, which the other
// issues only after finishing its reads of the prior vector).

#define DIMV 64
#define DTC  0.05f

using u64 = unsigned long long;

__device__ __forceinline__ u64 fma2(u64 a, u64 b, u64 c) {
    u64 d; asm("fma.rn.f32x2 %0, %1, %2, %3;" : "=l"(d) : "l"(a), "l"(b), "l"(c));
    return d;
}
__device__ __forceinline__ u64 add2(u64 a, u64 b) {
    u64 d; asm("add.rn.f32x2 %0, %1, %2;" : "=l"(d) : "l"(a), "l"(b));
    return d;
}

__global__ void __launch_bounds__(128, 1)
attractor_kernel(const float* __restrict__ x0,
                 const float* __restrict__ Wg,
                 const float* __restrict__ bg,
                 float* __restrict__ out,
                 int tsteps)
{
    __shared__ __align__(16) float xs[2][DIMV];    // x exchange buffer
    __shared__ __align__(16) float p1s[2][DIMV];   // p1 exchange buffer

    const int tid  = threadIdx.x;
    const int el   = tid >> 6;                     // local element 0/1
    const int i    = tid & 63;                     // row index
    const int h    = i >> 5;                       // my half: warp owns rows [32h,32h+32)
    const int elem = blockIdx.x * 2 + el;

    const int bmine  = 1 + el * 2 + h;             // I arrive: "my half written"
    const int bother = 1 + el * 2 + (1 - h);       // I sync:   "cross half written"
    const int ownu   = h * 8;                      // own half, ulonglong2 units (16B)
    const int crossu = 8 - h * 8;                  // cross half

    // ---- W row i, pre-scaled by DT, OWN-HALF COLUMNS FIRST ----
    // w2[0..15]  = cols [32h, 32h+32)   (paired, natural order within half)
    // w2[16..31] = cols of the other half
    u64 w2[32];
    {
        const float* wrow = Wg + i * DIMV;
        const int co = h * 32, cc = 32 - h * 32;
#pragma unroll
        for (int q = 0; q < 8; q++) {
            float4 a = *reinterpret_cast<const float4*>(wrow + co + 4 * q);
            float4 c = *reinterpret_cast<const float4*>(wrow + cc + 4 * q);
            float a0 = a.x * DTC, a1 = a.y * DTC, a2 = a.z * DTC, a3 = a.w * DTC;
            float c0 = c.x * DTC, c1 = c.y * DTC, c2 = c.z * DTC, c3 = c.w * DTC;
            asm("mov.b64 %0, {%1, %2};" : "=l"(w2[2*q])      : "f"(a0), "f"(a1));
            asm("mov.b64 %0, {%1, %2};" : "=l"(w2[2*q+1])    : "f"(a2), "f"(a3));
            asm("mov.b64 %0, {%1, %2};" : "=l"(w2[16+2*q])   : "f"(c0), "f"(c1));
            asm("mov.b64 %0, {%1, %2};" : "=l"(w2[16+2*q+1]) : "f"(c2), "f"(c3));
        }
    }
    const float db = DTC * bg[i];                  // DT * b_i
    float xi = x0[(size_t)elem * DIMV + i];
    float* outp = out + (size_t)elem * tsteps * DIMV + i;
    *outp = xi;                                    // x_0 stored up front

    // exchange + dot: store val, signal my half, consume own half under
    // syncwarp, consume cross half under the producer's arrive.
    auto xdot = [&](float* buf, float val) -> float {
        buf[i] = val;                              // STS my component
        asm volatile("bar.arrive %0, 64;" :: "r"(bmine) : "memory");
        __syncwarp();                              // own-half visibility (23 cyc)
        const ulonglong2* p16 = reinterpret_cast<const ulonglong2*>(buf);
        ulonglong2 vo[8], vc[8];
#pragma unroll
        for (int q = 0; q < 8; q++) vo[q] = p16[ownu + q];
        asm volatile("bar.sync %0, 64;" :: "r"(bother) : "memory");
#pragma unroll
        for (int q = 0; q < 8; q++) vc[q] = p16[crossu + q];
        u64 a0 = 0ull, a1 = 0ull, a2 = 0ull, a3 = 0ull;
#pragma unroll
        for (int q = 0; q < 8; q += 2) {           // own half (w2[0..15])
            a0 = fma2(w2[2*q + 0], vo[q].x,     a0);
            a1 = fma2(w2[2*q + 1], vo[q].y,     a1);
            a2 = fma2(w2[2*q + 2], vo[q + 1].x, a2);
            a3 = fma2(w2[2*q + 3], vo[q + 1].y, a3);
        }
#pragma unroll
        for (int q = 0; q < 8; q += 2) {           // cross half (w2[16..31])
            a0 = fma2(w2[16 + 2*q + 0], vc[q].x,     a0);
            a1 = fma2(w2[16 + 2*q + 1], vc[q].y,     a1);
            a2 = fma2(w2[16 + 2*q + 2], vc[q + 1].x, a2);
            a3 = fma2(w2[16 + 2*q + 3], vc[q + 1].y, a3);
        }
        u64 s = add2(add2(a0, a1), add2(a2, a3));
        float lo, hi;
        asm("mov.b64 {%0, %1}, %2;" : "=f"(lo), "=f"(hi) : "l"(s));
        return lo + hi;
    };

    // 99 updates: x_100 is never stored, so never computed.
#pragma unroll 1
    for (int t = 1; t < tsteps; t++) {
        const float c1xi = (1.0f - DTC) * xi;      // hides in xdot wait windows
        const float dxi  = DTC * xi;

        // exchange x + dot 1: dwx = DT*(Wx)
        float dwx  = xdot(xs[el], xi);
        float z    = dwx + db;                     // sign(DT*z) == sign(z)
        float relu = fmaxf(z, 0.f);
        float p    = relu - dxi;                   // p1 = DT*(relu(z) - x)

        // off critical path (scheduled into xdot-2's wait windows):
        bool  m     = z > 0.f;
        float sum   = relu + c1xi;                 // x + p1 (reassociated)
        float inner = sum - (0.5f * DTC) * p;      // x + p1 - (DT/2) p1

        // exchange p1 + dot 2: x' = inner + 0.5 * (m ? W'p1 : 0)
        float t2 = xdot(p1s[el], p);
        xi = fmaf(m ? t2 : 0.f, 0.5f, inner);

        outp += DIMV;
        *outp = xi;                                // off-chain trajectory store
    }
}

extern "C" void kernel_launch(void* const* d_in, const int* in_sizes, int n_in,
                              void* d_out, int out_size)
{
    const float* x0 = (const float*)d_in[0];   // (batch, 64)
    const float* W  = (const float*)d_in[1];   // (64, 64)
    const float* b  = (const float*)d_in[2];   // (64,)
    float* out = (float*)d_out;                // (batch, T, 64)

    int batch  = in_sizes[0] / DIMV;           // 256
    int tsteps = out_size / (batch * DIMV);    // 100

    attractor_kernel<<<batch / 2, 128>>>(x0, W, b, out, tsteps);
}

// round 11
// speedup vs baseline: 1.0307x; 1.0307x over previous
#include <cuda_runtime.h>

// AnalyticalBoundedLineAttractor — analytic piecewise-affine ODE integrator.
//
// Per step: z = Wx + b; m = (z>0); x' = x + p1 + p2 with
//   p1 = DT*(relu(z) - x),  p2 = (m .* (W'p1) - DT*p1)/2,  W' = DT*W.
// K = 2 Taylor terms (measured rel_err 4.6e-4 vs 1e-3 gate).
// Identity: W'p1 = W'relu(z) - DT*(W'x), so dot 2 runs on relu(z) and the
// -DT*W'x piece folds into local algebra (dwx = z - db, off-path).
//
// Architecture = measured best (R9): 2 elements per 128-thread CTA,
// grid=128 (one CTA/SM, 4 warps on 4 SMSPs), per-element NAMED 64-thread
// barriers, exchange = STS + bar + LDS.128 broadcast, dot = 16 LDS.128 +
// 32 fma.rn.f32x2 with 4 packed accumulators, 99 stored updates, unroll 1.
// R10's split-half arrive/sync gained nothing -> chain is ISSUE-bound,
// so R11 removes issues/serial-tail ops instead:
//  - DT*b folded into dot-1 accumulator init: z exits the reduce tree
//    directly (no FADD on chain).
//  - exchange relu(z) instead of p1: chain-1 tail = tree -> FMNMX -> STS
//    (FSUB moved off-path).
//  - dot-2 tail = sel -> fmaf only; all mask folds precomputed off-path.

#define DIMV 64
#define DTC  0.05f

using u64 = unsigned long long;

__device__ __forceinline__ u64 fma2(u64 a, u64 b, u64 c) {
    u64 d; asm("fma.rn.f32x2 %0, %1, %2, %3;" : "=l"(d) : "l"(a), "l"(b), "l"(c));
    return d;
}
__device__ __forceinline__ u64 add2(u64 a, u64 b) {
    u64 d; asm("add.rn.f32x2 %0, %1, %2;" : "=l"(d) : "l"(a), "l"(b));
    return d;
}
__device__ __forceinline__ u64 pack2(float lo, float hi) {
    u64 d; asm("mov.b64 %0, {%1, %2};" : "=l"(d) : "f"(lo), "f"(hi));
    return d;
}

__global__ void __launch_bounds__(128, 1)
attractor_kernel(const float* __restrict__ x0,
                 const float* __restrict__ Wg,
                 const float* __restrict__ bg,
                 float* __restrict__ out,
                 int tsteps)
{
    __shared__ __align__(16) float xs[2][DIMV];    // x exchange buffer
    __shared__ __align__(16) float rs[2][DIMV];    // relu(z) exchange buffer

    const int tid  = threadIdx.x;
    const int el   = tid >> 6;                     // local element 0/1
    const int i    = tid & 63;                     // row index
    const int elem = blockIdx.x * 2 + el;
    const int bar  = el + 1;                       // named barrier id

    // ---- W row i, pre-scaled by DT, as 32 packed f32x2 pairs ----
    u64 w2[32];
    {
        const float* wrow = Wg + i * DIMV;
#pragma unroll
        for (int q = 0; q < 16; q++) {
            float4 t = reinterpret_cast<const float4*>(wrow)[q];
            float s0 = t.x * DTC, s1 = t.y * DTC, s2 = t.z * DTC, s3 = t.w * DTC;
            asm("mov.b64 %0, {%1, %2};" : "=l"(w2[2*q])   : "f"(s0), "f"(s1));
            asm("mov.b64 %0, {%1, %2};" : "=l"(w2[2*q+1]) : "f"(s2), "f"(s3));
        }
    }
    const float db  = DTC * bg[i];                 // DT * b_i
    const u64 dbin  = pack2(db, 0.f);              // dot-1 accumulator seed
    float xi = x0[(size_t)elem * DIMV + i];

    xs[el][i] = xi;
    float* outp = out + (size_t)elem * tsteps * DIMV + i;
    *outp = xi;                                    // x_0 stored up front
    asm volatile("bar.sync %0, 64;" :: "r"(bar) : "memory");

    // dot(DT*W_row_i, buf) + seed: 16 x LDS.128 + 32 x fma.f32x2, 4 accs
    auto dot = [&](const float* buf, u64 seed) -> float {
        const ulonglong2* p16 = reinterpret_cast<const ulonglong2*>(buf);
        u64 a0 = seed, a1 = 0ull, a2 = 0ull, a3 = 0ull;
#pragma unroll
        for (int q = 0; q < 16; q += 2) {
            ulonglong2 v0 = p16[q];
            ulonglong2 v1 = p16[q + 1];
            a0 = fma2(w2[2*q + 0], v0.x, a0);
            a1 = fma2(w2[2*q + 1], v0.y, a1);
            a2 = fma2(w2[2*q + 2], v1.x, a2);
            a3 = fma2(w2[2*q + 3], v1.y, a3);
        }
        u64 s = add2(add2(a0, a1), add2(a2, a3));
        float lo, hi;
        asm("mov.b64 {%0, %1}, %2;" : "=f"(lo), "=f"(hi) : "l"(s));
        return lo + hi;
    };

    // 99 updates: x_100 is never stored, so never computed.
#pragma unroll 1
    for (int t = 1; t < tsteps; t++) {
        const float c1xi = (1.0f - DTC) * xi;      // hides in dot-1 window
        const float dxi  = DTC * xi;

        // dot 1: z = (W'x)_i + DT*b_i straight out of the tree
        float z    = dot(xs[el], dbin);
        float relu = fmaxf(z, 0.f);                // FMNMX, lat 4
        rs[el][i]  = relu;                         // exchange relu(z)
        asm volatile("bar.sync %0, 64;" :: "r"(bar) : "memory");

        // off critical path (overlaps barrier + dot-2 LDS/FMA stream):
        //   p1 = relu - DT*x ; dwx = z - db
        //   inner2 = x + p1 - (DT/2) p1 - m * (DT/2) dwx
        bool  m     = z > 0.f;
        float p1    = relu - dxi;
        float dwx   = z - db;
        float inner = fmaf(-0.5f * DTC, p1, relu + c1xi);
        float inner2 = inner - (m ? 0.5f * DTC * dwx : 0.f);

        // dot 2: t2 = (W' relu)_i ; x' = inner2 + 0.5 * (m ? t2 : 0)
        float t2 = dot(rs[el], 0ull);
        xi = fmaf(m ? t2 : 0.f, 0.5f, inner2);     // sel + fma only

        xs[el][i] = xi;                            // xs readers retired at bar above
        outp += DIMV;
        *outp = xi;                                // off-chain trajectory store
        asm volatile("bar.sync %0, 64;" :: "r"(bar) : "memory");
    }
}

extern "C" void kernel_launch(void* const* d_in, const int* in_sizes, int n_in,
                              void* d_out, int out_size)
{
    const float* x0 = (const float*)d_in[0];   // (batch, 64)
    const float* W  = (const float*)d_in[1];   // (64, 64)
    const float* b  = (const float*)d_in[2];   // (64,)
    float* out = (float*)d_out;                // (batch, T, 64)

    int batch  = in_sizes[0] / DIMV;           // 256
    int tsteps = out_size / (batch * DIMV);    // 100

    attractor_kernel<<<batch / 2, 128>>>(x0, W, b, out, tsteps);
}